// round 3
// baseline (speedup 1.0000x reference)
#include <cuda_runtime.h>

#define NMAX 50000
#define EMAX 640000
#define D    128

// ---- scratch (device globals: no allocation allowed) ----
__device__ int   g_deg[NMAX];
__device__ int   g_rowptr[NMAX + 1];
__device__ int   g_cursor[NMAX];
__device__ int   g_col[EMAX];
__device__ float g_inv[NMAX];
__device__ float g_agg[(size_t)NMAX * D];
__device__ float g_h[(size_t)NMAX * D];

// ---------------- CSR build ----------------
__global__ void k_zero_deg(int Nn) {
    int i = blockIdx.x * blockDim.x + threadIdx.x;
    if (i < Nn) g_deg[i] = 0;
}

__global__ void k_deg(const int* __restrict__ dst, int E, int Nn) {
    int e = blockIdx.x * blockDim.x + threadIdx.x;
    if (e < E) {
        unsigned d = (unsigned)dst[e];
        if (d < (unsigned)Nn) atomicAdd(&g_deg[d], 1);
    }
}

// single-block exclusive scan over degrees; also writes cursor + inv_deg
__global__ void k_scan(int Nn) {
    __shared__ int sm[1024];
    int t = threadIdx.x;
    int CH = (Nn + 1023) / 1024;
    int beg = t * CH;
    int end = beg + CH; if (end > Nn) end = Nn;
    int s = 0;
    for (int i = beg; i < end; i++) s += g_deg[i];
    sm[t] = s;
    __syncthreads();
    for (int off = 1; off < 1024; off <<= 1) {
        int v = (t >= off) ? sm[t - off] : 0;
        __syncthreads();
        sm[t] += v;
        __syncthreads();
    }
    int base = sm[t] - s;           // exclusive prefix of this thread's chunk
    int total = sm[1023];
    int run = base;
    for (int i = beg; i < end; i++) {
        int d = g_deg[i];
        g_rowptr[i] = run;
        g_cursor[i] = run;
        g_inv[i]    = 1.0f / (float)(d > 0 ? d : 1);
        run += d;
    }
    if (t == 0) g_rowptr[Nn] = total;
}

__global__ void k_fill(const int* __restrict__ src,
                       const int* __restrict__ dst, int E, int Nn) {
    int e = blockIdx.x * blockDim.x + threadIdx.x;
    if (e < E) {
        unsigned d = (unsigned)dst[e];
        unsigned s = (unsigned)src[e];
        if (d < (unsigned)Nn && s < (unsigned)Nn) {
            int p = atomicAdd(&g_cursor[d], 1);
            g_col[p] = (int)s;
        }
    }
}

// ---------------- mean aggregation: one warp per destination node ----------------
// IN_H: read from g_h instead of the X parameter. Output is always g_agg.
template <bool IN_H>
__global__ void k_agg(const float* __restrict__ X, int Nn) {
    int warp = (blockIdx.x * blockDim.x + threadIdx.x) >> 5;
    int lane = threadIdx.x & 31;
    if (warp >= Nn) return;
    const float* __restrict__ in = IN_H ? (const float*)g_h : X;
    int r0 = g_rowptr[warp];
    int r1 = g_rowptr[warp + 1];
    float4 acc = make_float4(0.f, 0.f, 0.f, 0.f);
    for (int e = r0; e < r1; e++) {
        int s = g_col[e];
        float4 v = *(const float4*)(in + (size_t)s * D + lane * 4);
        acc.x += v.x; acc.y += v.y; acc.z += v.z; acc.w += v.w;
    }
    float inv = g_inv[warp];
    acc.x *= inv; acc.y *= inv; acc.z *= inv; acc.w *= inv;
    *(float4*)(g_agg + (size_t)warp * D + lane * 4) = acc;
}

// ---------------- fused dual GEMM: C = g_agg@W1^T + A2@W2^T + bias (opt relu) ----
// A2_H: second operand is g_h (else the A2 parameter).
// OUT_H: write result to g_h (else the C parameter).
template <bool RELU, bool A2_H, bool OUT_H>
__global__ void __launch_bounds__(256, 2)
k_gemm(const float* __restrict__ A2p,
       const float* __restrict__ W1, const float* __restrict__ W2,
       const float* __restrict__ bias, float* __restrict__ Cp, int Nn)
{
    constexpr int BM = 128, BN = 128, BK = 16, TM = 8, TN = 8;
    __shared__ float As[BK][BM];
    __shared__ float Bs[BK][BN];

    const float* __restrict__ A2 = A2_H ? (const float*)g_h : A2p;
    float* __restrict__ C = OUT_H ? (float*)g_h : Cp;

    int tid = threadIdx.x;          // 256 threads
    int tm  = tid / 16;             // 0..15
    int tn  = tid % 16;             // 0..15
    int m0  = blockIdx.x * BM;

    float acc[TM][TN];
#pragma unroll
    for (int i = 0; i < TM; i++)
#pragma unroll
        for (int j = 0; j < TN; j++) acc[i][j] = 0.f;

#pragma unroll
    for (int seg = 0; seg < 2; seg++) {
        const float* A = seg ? A2 : (const float*)g_agg;
        const float* W = seg ? W2 : W1;
        for (int k0 = 0; k0 < D; k0 += BK) {
            // A tile (128 rows x 16 k) -> As[k][m] transposed
#pragma unroll
            for (int l = 0; l < 2; l++) {
                int idx = tid + l * 256;    // 0..511 float4 slots
                int row = idx >> 2;         // 0..127
                int kc4 = idx & 3;
                int gm  = m0 + row;
                float4 v = make_float4(0.f, 0.f, 0.f, 0.f);
                if (gm < Nn) v = *(const float4*)(A + (size_t)gm * D + k0 + kc4 * 4);
                As[kc4 * 4 + 0][row] = v.x;
                As[kc4 * 4 + 1][row] = v.y;
                As[kc4 * 4 + 2][row] = v.z;
                As[kc4 * 4 + 3][row] = v.w;
            }
            // W tile (128 outs x 16 k) -> Bs[k][o]
#pragma unroll
            for (int l = 0; l < 2; l++) {
                int idx = tid + l * 256;
                int o   = idx >> 2;
                int kc4 = idx & 3;
                float4 v = *(const float4*)(W + (size_t)o * D + k0 + kc4 * 4);
                Bs[kc4 * 4 + 0][o] = v.x;
                Bs[kc4 * 4 + 1][o] = v.y;
                Bs[kc4 * 4 + 2][o] = v.z;
                Bs[kc4 * 4 + 3][o] = v.w;
            }
            __syncthreads();
#pragma unroll
            for (int k = 0; k < BK; k++) {
                float ra[TM], rb[TN];
#pragma unroll
                for (int i = 0; i < TM; i++) ra[i] = As[k][tm * TM + i];
#pragma unroll
                for (int j = 0; j < TN; j++) rb[j] = Bs[k][tn * TN + j];
#pragma unroll
                for (int i = 0; i < TM; i++)
#pragma unroll
                    for (int j = 0; j < TN; j++)
                        acc[i][j] += ra[i] * rb[j];
            }
            __syncthreads();
        }
    }

    // epilogue: + bias, optional relu, store
#pragma unroll
    for (int i = 0; i < TM; i++) {
        int gm = m0 + tm * TM + i;
        if (gm >= Nn) continue;
#pragma unroll
        for (int j = 0; j < TN; j += 4) {
            int o = tn * TN + j;
            float4 r;
            r.x = acc[i][j + 0] + bias[o + 0];
            r.y = acc[i][j + 1] + bias[o + 1];
            r.z = acc[i][j + 2] + bias[o + 2];
            r.w = acc[i][j + 3] + bias[o + 3];
            if (RELU) {
                r.x = fmaxf(r.x, 0.f); r.y = fmaxf(r.y, 0.f);
                r.z = fmaxf(r.z, 0.f); r.w = fmaxf(r.w, 0.f);
            }
            *(float4*)(C + (size_t)gm * D + o) = r;
        }
    }
}

extern "C" void kernel_launch(void* const* d_in, const int* in_sizes, int n_in,
                              void* d_out, int out_size)
{
    const float* x   = (const float*)d_in[0];
    const int*   ei  = (const int*)d_in[1];       // int32! (JAX x64 disabled)
    const float* w1l = (const float*)d_in[2];
    const float* b1  = (const float*)d_in[3];
    const float* w1r = (const float*)d_in[4];
    const float* w2l = (const float*)d_in[5];
    const float* b2  = (const float*)d_in[6];
    const float* w2r = (const float*)d_in[7];
    float*       out = (float*)d_out;

    int Nn = in_sizes[0] / D;
    int E  = in_sizes[1] / 2;
    const int* src = ei;
    const int* dst = ei + E;

    // ---- CSR build (shared by both layers) ----
    k_zero_deg<<<(Nn + 255) / 256, 256>>>(Nn);
    k_deg<<<(E + 255) / 256, 256>>>(dst, E, Nn);
    k_scan<<<1, 1024>>>(Nn);
    k_fill<<<(E + 255) / 256, 256>>>(src, dst, E, Nn);

    int aggBlocks  = (Nn * 32 + 255) / 256;
    int gemmBlocks = (Nn + 127) / 128;

    // ---- layer 1: agg(x) -> g_agg ; h = relu(g_agg@w1l^T + b1 + x@w1r^T) -> g_h
    k_agg<false><<<aggBlocks, 256>>>(x, Nn);
    k_gemm<true, false, true><<<gemmBlocks, 256>>>(x, w1l, w1r, b1, nullptr, Nn);

    // ---- layer 2: agg(g_h) -> g_agg ; out = g_agg@w2l^T + b2 + g_h@w2r^T
    k_agg<true><<<aggBlocks, 256>>>(nullptr, Nn);
    k_gemm<false, true, false><<<gemmBlocks, 256>>>(nullptr, w2l, w2r, b2, out, Nn);
}

// round 5
// speedup vs baseline: 1.8703x; 1.8703x over previous
#include <cuda_runtime.h>
#include <cuda_bf16.h>
#include <cstdint>

#define NMAX 50000
#define EMAX 640000
#define D    128
#define PADK 40   // padded smem row (bf16 elems) -> conflict-free frag loads

// ---- scratch (device globals; no allocation allowed) ----
__device__ int   g_deg[NMAX];
__device__ int   g_rowptr[NMAX + 1];
__device__ int   g_cursor[NMAX];
__device__ int   g_col[EMAX];
__device__ float g_inv[NMAX];
__device__ int   g_bsum[256];
__device__ int   g_boff[256];

__device__ __align__(16) float         g_h [(size_t)NMAX * D];   // layer-1 output fp32
__device__ __align__(16) __nv_bfloat16 g_gh[(size_t)NMAX * D];   // agg split hi
__device__ __align__(16) __nv_bfloat16 g_gl[(size_t)NMAX * D];   // agg split lo
__device__ __align__(16) __nv_bfloat16 g_xh[(size_t)NMAX * D];   // x split hi
__device__ __align__(16) __nv_bfloat16 g_xl[(size_t)NMAX * D];
__device__ __align__(16) __nv_bfloat16 g_hh[(size_t)NMAX * D];   // h split hi
__device__ __align__(16) __nv_bfloat16 g_hl[(size_t)NMAX * D];
__device__ __align__(16) __nv_bfloat16 g_wh[4 * D * D];          // w1l,w1r,w2l,w2r hi
__device__ __align__(16) __nv_bfloat16 g_wl[4 * D * D];          // lo

// ============================ CSR build ============================
__global__ void k_zero_deg(int Nn) {
    int i = blockIdx.x * blockDim.x + threadIdx.x;
    if (i < Nn) g_deg[i] = 0;
}

__global__ void k_deg(const int* __restrict__ dst, int E, int Nn) {
    int e = blockIdx.x * blockDim.x + threadIdx.x;
    if (e < E) {
        unsigned d = (unsigned)dst[e];
        if (d < (unsigned)Nn) atomicAdd(&g_deg[d], 1);
    }
}

// per-block degree sums
__global__ void k_bsum(int Nn) {
    __shared__ int sm[256];
    int t = threadIdx.x;
    int i = blockIdx.x * 256 + t;
    sm[t] = (i < Nn) ? g_deg[i] : 0;
    __syncthreads();
    for (int off = 128; off > 0; off >>= 1) {
        if (t < off) sm[t] += sm[t + off];
        __syncthreads();
    }
    if (t == 0) g_bsum[blockIdx.x] = sm[0];
}

// single-block scan of block sums (NB <= 256)
__global__ void k_bscan(int NB, int Nn) {
    __shared__ int sm[256];
    int t = threadIdx.x;
    int v = (t < NB) ? g_bsum[t] : 0;
    sm[t] = v;
    __syncthreads();
    for (int off = 1; off < 256; off <<= 1) {
        int u = (t >= off) ? sm[t - off] : 0;
        __syncthreads();
        sm[t] += u;
        __syncthreads();
    }
    g_boff[t] = sm[t] - v;                 // exclusive
    if (t == 255) g_rowptr[Nn] = sm[255];  // total
}

// finalize rowptr / cursor / inv with intra-block scan + block offset
__global__ void k_rowptr(int Nn) {
    __shared__ int sm[256];
    int t = threadIdx.x;
    int i = blockIdx.x * 256 + t;
    int d = (i < Nn) ? g_deg[i] : 0;
    sm[t] = d;
    __syncthreads();
    for (int off = 1; off < 256; off <<= 1) {
        int u = (t >= off) ? sm[t - off] : 0;
        __syncthreads();
        sm[t] += u;
        __syncthreads();
    }
    if (i < Nn) {
        int start = g_boff[blockIdx.x] + sm[t] - d;
        g_rowptr[i] = start;
        g_cursor[i] = start;
        g_inv[i]    = 1.0f / (float)(d > 0 ? d : 1);
    }
}

__global__ void k_fill(const int* __restrict__ src,
                       const int* __restrict__ dst, int E, int Nn) {
    int e = blockIdx.x * blockDim.x + threadIdx.x;
    if (e < E) {
        unsigned d = (unsigned)dst[e];
        unsigned s = (unsigned)src[e];
        if (d < (unsigned)Nn && s < (unsigned)Nn) {
            int p = atomicAdd(&g_cursor[d], 1);
            g_col[p] = (int)s;
        }
    }
}

// ============================ splits ============================
__device__ __forceinline__ void split2(float a, float b,
                                       __nv_bfloat162& hi, __nv_bfloat162& lo) {
    __nv_bfloat16 ha = __float2bfloat16_rn(a);
    __nv_bfloat16 hb = __float2bfloat16_rn(b);
    float la = a - __bfloat162float(ha);
    float lb = b - __bfloat162float(hb);
    hi = __halves2bfloat162(ha, hb);
    lo = __halves2bfloat162(__float2bfloat16_rn(la), __float2bfloat16_rn(lb));
}

__global__ void k_split_x(const float* __restrict__ x, int total4) {
    int i = blockIdx.x * blockDim.x + threadIdx.x;   // one float4 per thread
    if (i >= total4) return;
    float4 v = *(const float4*)(x + (size_t)i * 4);
    __nv_bfloat162 h0, l0, h1, l1;
    split2(v.x, v.y, h0, l0);
    split2(v.z, v.w, h1, l1);
    *(__nv_bfloat162*)(g_xh + (size_t)i * 4)     = h0;
    *(__nv_bfloat162*)(g_xh + (size_t)i * 4 + 2) = h1;
    *(__nv_bfloat162*)(g_xl + (size_t)i * 4)     = l0;
    *(__nv_bfloat162*)(g_xl + (size_t)i * 4 + 2) = l1;
}

__global__ void k_splitW(const float* __restrict__ w0, const float* __restrict__ w1,
                         const float* __restrict__ w2, const float* __restrict__ w3) {
    int i = blockIdx.x * blockDim.x + threadIdx.x;   // 0..16383
    if (i >= D * D) return;
    const float* srcs[4] = {w0, w1, w2, w3};
#pragma unroll
    for (int m = 0; m < 4; m++) {
        float v = srcs[m][i];
        __nv_bfloat16 h = __float2bfloat16_rn(v);
        g_wh[m * D * D + i] = h;
        g_wl[m * D * D + i] = __float2bfloat16_rn(v - __bfloat162float(h));
    }
}

// ============== mean aggregation: one warp per node, split-bf16 output ==============
template <bool IN_H>
__global__ void k_agg(const float* __restrict__ X, int Nn) {
    int node = (blockIdx.x * blockDim.x + threadIdx.x) >> 5;
    int lane = threadIdx.x & 31;
    if (node >= Nn) return;
    const float* __restrict__ in = IN_H ? (const float*)g_h : X;
    int r0 = g_rowptr[node];
    int r1 = g_rowptr[node + 1];
    float4 acc0 = make_float4(0.f, 0.f, 0.f, 0.f);
    float4 acc1 = make_float4(0.f, 0.f, 0.f, 0.f);
    int e = r0;
    for (; e + 1 < r1; e += 2) {
        int s0 = g_col[e];
        int s1 = g_col[e + 1];
        float4 v0 = *(const float4*)(in + (size_t)s0 * D + lane * 4);
        float4 v1 = *(const float4*)(in + (size_t)s1 * D + lane * 4);
        acc0.x += v0.x; acc0.y += v0.y; acc0.z += v0.z; acc0.w += v0.w;
        acc1.x += v1.x; acc1.y += v1.y; acc1.z += v1.z; acc1.w += v1.w;
    }
    if (e < r1) {
        int s0 = g_col[e];
        float4 v0 = *(const float4*)(in + (size_t)s0 * D + lane * 4);
        acc0.x += v0.x; acc0.y += v0.y; acc0.z += v0.z; acc0.w += v0.w;
    }
    float inv = g_inv[node];
    float a = (acc0.x + acc1.x) * inv;
    float b = (acc0.y + acc1.y) * inv;
    float c = (acc0.z + acc1.z) * inv;
    float d = (acc0.w + acc1.w) * inv;
    __nv_bfloat162 h0, l0, h1, l1;
    split2(a, b, h0, l0);
    split2(c, d, h1, l1);
    size_t base = (size_t)node * D + lane * 4;
    *(__nv_bfloat162*)(g_gh + base)     = h0;
    *(__nv_bfloat162*)(g_gh + base + 2) = h1;
    *(__nv_bfloat162*)(g_gl + base)     = l0;
    *(__nv_bfloat162*)(g_gl + base + 2) = l1;
}

// ============== tensor-core fused dual GEMM (split-bf16, virtual K=768) ==============
// C = A1@W1^T + A2@W2^T + bias   where each product = Ah@Wh + Al@Wh + Ah@Wl
__device__ __forceinline__ void mma16816(float c[4], uint32_t a0, uint32_t a1,
                                         uint32_t a2, uint32_t a3,
                                         uint32_t b0, uint32_t b1) {
    asm volatile(
        "mma.sync.aligned.m16n8k16.row.col.f32.bf16.bf16.f32 "
        "{%0,%1,%2,%3}, {%4,%5,%6,%7}, {%8,%9}, {%0,%1,%2,%3};\n"
        : "+f"(c[0]), "+f"(c[1]), "+f"(c[2]), "+f"(c[3])
        : "r"(a0), "r"(a1), "r"(a2), "r"(a3), "r"(b0), "r"(b1));
}

template <int LAYER>   // 1: relu, writes g_h + g_hh/g_hl ; 2: writes outp fp32
__global__ void __launch_bounds__(256, 2)
k_mma(const float* __restrict__ bias, float* __restrict__ outp, int Nn)
{
    __shared__ __nv_bfloat16 As[2][128 * PADK];
    __shared__ __nv_bfloat16 Bs[2][128 * PADK];

    const __nv_bfloat16* A2h = (LAYER == 1) ? g_xh : g_hh;
    const __nv_bfloat16* A2l = (LAYER == 1) ? g_xl : g_hl;
    const int wl = (LAYER == 1) ? 0 : 2;   // w?l index
    const int wr = (LAYER == 1) ? 1 : 3;   // w?r index
    const __nv_bfloat16* Wlh = g_wh + wl * D * D;
    const __nv_bfloat16* Wll = g_wl + wl * D * D;
    const __nv_bfloat16* Wrh = g_wh + wr * D * D;
    const __nv_bfloat16* Wrl = g_wl + wr * D * D;

    // virtual-K slabs (6 x 128): seg1 Ah@Wh, Al@Wh, Ah@Wl ; seg2 same with A2/Wr
    const __nv_bfloat16* Aslab[6] = {g_gh, g_gl, g_gh, A2h, A2l, A2h};
    const __nv_bfloat16* Wslab[6] = {Wlh,  Wlh,  Wll,  Wrh,  Wrh,  Wrl};

    int tid = threadIdx.x;
    int m0  = blockIdx.x * 128;
    int warp = tid >> 5, lane = tid & 31;
    int wm = (warp >> 2) * 64;      // warp m-offset (2 warps in m)
    int wn = (warp & 3) * 32;       // warp n-offset (4 warps in n)
    int g  = lane >> 2, ctg = lane & 3;

    float acc[4][4][4] = {};

    uint4 pa[2], pb[2];
    auto ldg_step = [&](int s) {
        int slab = s >> 2, koff = (s & 3) * 32;
        const __nv_bfloat16* Ap = Aslab[slab];
        const __nv_bfloat16* Wp = Wslab[slab];
#pragma unroll
        for (int l = 0; l < 2; l++) {
            int u = tid + l * 256;
            int row = u >> 2, kq = u & 3;
            int gm = m0 + row;
            uint4 va = make_uint4(0u, 0u, 0u, 0u);
            if (gm < Nn) va = *(const uint4*)(Ap + (size_t)gm * D + koff + kq * 8);
            pa[l] = va;
            pb[l] = *(const uint4*)(Wp + row * D + koff + kq * 8);
        }
    };
    auto sts_step = [&](int buf) {
#pragma unroll
        for (int l = 0; l < 2; l++) {
            int u = tid + l * 256;
            int row = u >> 2, kq = u & 3;
            *(uint4*)(&As[buf][row * PADK + kq * 8]) = pa[l];
            *(uint4*)(&Bs[buf][row * PADK + kq * 8]) = pb[l];
        }
    };
    auto compute = [&](int buf) {
#pragma unroll
        for (int p = 0; p < 2; p++) {          // two k16 phases per BK=32
            uint32_t bfr[4][2];
#pragma unroll
            for (int ni = 0; ni < 4; ni++) {
                int n = wn + ni * 8 + g;
                const __nv_bfloat16* bp = &Bs[buf][n * PADK + p * 16 + ctg * 2];
                bfr[ni][0] = *(const uint32_t*)bp;
                bfr[ni][1] = *(const uint32_t*)(bp + 8);
            }
#pragma unroll
            for (int mi = 0; mi < 4; mi++) {
                int r = wm + mi * 16 + g;
                const __nv_bfloat16* ap = &As[buf][r * PADK + p * 16 + ctg * 2];
                uint32_t a0 = *(const uint32_t*)ap;
                uint32_t a1 = *(const uint32_t*)(ap + 8 * PADK);
                uint32_t a2 = *(const uint32_t*)(ap + 8);
                uint32_t a3 = *(const uint32_t*)(ap + 8 * PADK + 8);
#pragma unroll
                for (int ni = 0; ni < 4; ni++)
                    mma16816(acc[mi][ni], a0, a1, a2, a3, bfr[ni][0], bfr[ni][1]);
            }
        }
    };

    ldg_step(0);
    sts_step(0);
    __syncthreads();
    for (int s = 0; s < 24; s++) {
        if (s < 23) ldg_step(s + 1);
        compute(s & 1);
        if (s < 23) sts_step((s + 1) & 1);
        __syncthreads();
    }

    // epilogue
#pragma unroll
    for (int mi = 0; mi < 4; mi++) {
        int r0 = m0 + wm + mi * 16 + g;
        int r1 = r0 + 8;
#pragma unroll
        for (int ni = 0; ni < 4; ni++) {
            int col = wn + ni * 8 + ctg * 2;
            float2 b2 = *(const float2*)(bias + col);
            float v00 = acc[mi][ni][0] + b2.x, v01 = acc[mi][ni][1] + b2.y;
            float v10 = acc[mi][ni][2] + b2.x, v11 = acc[mi][ni][3] + b2.y;
            if (LAYER == 1) {
                v00 = fmaxf(v00, 0.f); v01 = fmaxf(v01, 0.f);
                v10 = fmaxf(v10, 0.f); v11 = fmaxf(v11, 0.f);
                if (r0 < Nn) {
                    size_t o = (size_t)r0 * D + col;
                    *(float2*)(g_h + o) = make_float2(v00, v01);
                    __nv_bfloat162 h2, l2; split2(v00, v01, h2, l2);
                    *(__nv_bfloat162*)(g_hh + o) = h2;
                    *(__nv_bfloat162*)(g_hl + o) = l2;
                }
                if (r1 < Nn) {
                    size_t o = (size_t)r1 * D + col;
                    *(float2*)(g_h + o) = make_float2(v10, v11);
                    __nv_bfloat162 h2, l2; split2(v10, v11, h2, l2);
                    *(__nv_bfloat162*)(g_hh + o) = h2;
                    *(__nv_bfloat162*)(g_hl + o) = l2;
                }
            } else {
                if (r0 < Nn) *(float2*)(outp + (size_t)r0 * D + col) = make_float2(v00, v01);
                if (r1 < Nn) *(float2*)(outp + (size_t)r1 * D + col) = make_float2(v10, v11);
            }
        }
    }
}

// ============================ launch ============================
extern "C" void kernel_launch(void* const* d_in, const int* in_sizes, int n_in,
                              void* d_out, int out_size)
{
    const float* x   = (const float*)d_in[0];
    const int*   ei  = (const int*)d_in[1];       // int32 (JAX x64 disabled)
    const float* w1l = (const float*)d_in[2];
    const float* b1  = (const float*)d_in[3];
    const float* w1r = (const float*)d_in[4];
    const float* w2l = (const float*)d_in[5];
    const float* b2  = (const float*)d_in[6];
    const float* w2r = (const float*)d_in[7];
    float*       out = (float*)d_out;

    int Nn = in_sizes[0] / D;
    int E  = in_sizes[1] / 2;
    const int* src = ei;
    const int* dst = ei + E;
    int NB = (Nn + 255) / 256;

    // CSR build
    k_zero_deg<<<NB, 256>>>(Nn);
    k_deg<<<(E + 255) / 256, 256>>>(dst, E, Nn);
    k_bsum<<<NB, 256>>>(Nn);
    k_bscan<<<1, 256>>>(NB, Nn);
    k_rowptr<<<NB, 256>>>(Nn);
    k_fill<<<(E + 255) / 256, 256>>>(src, dst, E, Nn);

    // operand splits
    k_split_x<<<(Nn * (D / 4) + 255) / 256, 256>>>(x, Nn * (D / 4));
    k_splitW<<<(D * D + 255) / 256, 256>>>(w1l, w1r, w2l, w2r);

    int aggBlocks  = (Nn * 32 + 255) / 256;
    int gemmBlocks = (Nn + 127) / 128;

    // layer 1: agg(x) -> splits ; h = relu(agg@w1l^T + b1 + x@w1r^T)
    k_agg<false><<<aggBlocks, 256>>>(x, Nn);
    k_mma<1><<<gemmBlocks, 256>>>(b1, nullptr, Nn);

    // layer 2: agg(h) -> splits ; out = agg@w2l^T + b2 + h@w2r^T
    k_agg<true><<<aggBlocks, 256>>>(nullptr, Nn);
    k_mma<2><<<gemmBlocks, 256>>>(b2, out, Nn);
}

// round 6
// speedup vs baseline: 1.8951x; 1.0132x over previous
#include <cuda_runtime.h>
#include <cuda_bf16.h>
#include <cstdint>

#define NMAX 50000
#define EMAX 640000
#define D    128
#define PADK 40   // padded smem row (bf16 elems) -> conflict-free frag loads

// ---- scratch (device globals; no allocation allowed) ----
__device__ int   g_deg[NMAX];        // zeroed by k_assign for next replay
__device__ int   g_rowptr[NMAX];
__device__ int   g_rowend[NMAX];
__device__ int   g_cursor[NMAX];
__device__ int   g_col[EMAX];
__device__ float g_inv[NMAX];
__device__ int   g_total;

__device__ __align__(16) __nv_bfloat16 g_gh[(size_t)NMAX * D];   // agg split hi
__device__ __align__(16) __nv_bfloat16 g_gl[(size_t)NMAX * D];   // agg split lo
__device__ __align__(16) __nv_bfloat16 g_xh[(size_t)NMAX * D];   // x split hi
__device__ __align__(16) __nv_bfloat16 g_xl[(size_t)NMAX * D];
__device__ __align__(16) __nv_bfloat16 g_hh[(size_t)NMAX * D];   // h split hi
__device__ __align__(16) __nv_bfloat16 g_hl[(size_t)NMAX * D];
__device__ __align__(16) __nv_bfloat16 g_wh[4 * D * D];          // w1l,w1r,w2l,w2r hi
__device__ __align__(16) __nv_bfloat16 g_wl[4 * D * D];          // lo

// ============================ splits helper ============================
__device__ __forceinline__ void split2(float a, float b,
                                       __nv_bfloat162& hi, __nv_bfloat162& lo) {
    __nv_bfloat16 ha = __float2bfloat16_rn(a);
    __nv_bfloat16 hb = __float2bfloat16_rn(b);
    float la = a - __bfloat162float(ha);
    float lb = b - __bfloat162float(hb);
    hi = __halves2bfloat162(ha, hb);
    lo = __halves2bfloat162(__float2bfloat16_rn(la), __float2bfloat16_rn(lb));
}

// ============================ CSR build (scan-free) ============================
__global__ void k_deg(const int* __restrict__ dst, int E, int Nn) {
    int e = blockIdx.x * blockDim.x + threadIdx.x;
    if (e == 0) g_total = 0;               // reset ticket for k_assign
    if (e < E) {
        unsigned d = (unsigned)dst[e];
        if (d < (unsigned)Nn) atomicAdd(&g_deg[d], 1);
    }
}

// segment starts via atomic ticket (order irrelevant for gather CSR)
__global__ void k_assign(int Nn) {
    int i = blockIdx.x * blockDim.x + threadIdx.x;
    if (i < Nn) {
        int d = g_deg[i];
        int start = atomicAdd(&g_total, d);
        g_rowptr[i] = start;
        g_cursor[i] = start;
        g_rowend[i] = start + d;
        g_inv[i]    = 1.0f / (float)(d > 0 ? d : 1);
        g_deg[i]    = 0;                   // clean for next replay
    }
}

// fused: CSR fill + x split + W split, dispatched by block range
__global__ void k_fill_split(const int* __restrict__ src,
                             const int* __restrict__ dst, int E, int Nn,
                             const float* __restrict__ x,
                             const float* __restrict__ w0, const float* __restrict__ w1,
                             const float* __restrict__ w2, const float* __restrict__ w3,
                             int FB, int XB) {
    int bid = blockIdx.x;
    int tid = threadIdx.x;
    if (bid < FB) {
        int e = bid * 256 + tid;
        if (e < E) {
            unsigned d = (unsigned)dst[e];
            unsigned s = (unsigned)src[e];
            if (d < (unsigned)Nn && s < (unsigned)Nn) {
                int p = atomicAdd(&g_cursor[d], 1);
                g_col[p] = (int)s;
            }
        }
    } else if (bid < FB + XB) {
        int i = (bid - FB) * 256 + tid;    // one float4 per thread
        int total4 = Nn * (D / 4);
        if (i < total4) {
            float4 v = *(const float4*)(x + (size_t)i * 4);
            __nv_bfloat162 h0, l0, h1, l1;
            split2(v.x, v.y, h0, l0);
            split2(v.z, v.w, h1, l1);
            *(__nv_bfloat162*)(g_xh + (size_t)i * 4)     = h0;
            *(__nv_bfloat162*)(g_xh + (size_t)i * 4 + 2) = h1;
            *(__nv_bfloat162*)(g_xl + (size_t)i * 4)     = l0;
            *(__nv_bfloat162*)(g_xl + (size_t)i * 4 + 2) = l1;
        }
    } else {
        int i = (bid - FB - XB) * 256 + tid;   // 0..16383
        if (i < D * D) {
            const float* srcs[4] = {w0, w1, w2, w3};
#pragma unroll
            for (int m = 0; m < 4; m++) {
                float v = srcs[m][i];
                __nv_bfloat16 h = __float2bfloat16_rn(v);
                g_wh[m * D * D + i] = h;
                g_wl[m * D * D + i] = __float2bfloat16_rn(v - __bfloat162float(h));
            }
        }
    }
}

// ============== mean aggregation: one warp per node, split-bf16 output ==============
// IN_H: input is the hh/hl split pair (layer 2); else fp32 X (layer 1).
template <bool IN_H>
__global__ void k_agg(const float* __restrict__ X, int Nn) {
    int node = (blockIdx.x * blockDim.x + threadIdx.x) >> 5;
    int lane = threadIdx.x & 31;
    if (node >= Nn) return;
    int r0 = g_rowptr[node];
    int r1 = g_rowend[node];
    float4 acc0 = make_float4(0.f, 0.f, 0.f, 0.f);
    float4 acc1 = make_float4(0.f, 0.f, 0.f, 0.f);

    auto loadv = [&](int s) -> float4 {
        if (IN_H) {
            size_t o = (size_t)s * D + lane * 4;
            __nv_bfloat162 h0 = *(const __nv_bfloat162*)(g_hh + o);
            __nv_bfloat162 h1 = *(const __nv_bfloat162*)(g_hh + o + 2);
            __nv_bfloat162 l0 = *(const __nv_bfloat162*)(g_hl + o);
            __nv_bfloat162 l1 = *(const __nv_bfloat162*)(g_hl + o + 2);
            return make_float4(__bfloat162float(h0.x) + __bfloat162float(l0.x),
                               __bfloat162float(h0.y) + __bfloat162float(l0.y),
                               __bfloat162float(h1.x) + __bfloat162float(l1.x),
                               __bfloat162float(h1.y) + __bfloat162float(l1.y));
        } else {
            return *(const float4*)(X + (size_t)s * D + lane * 4);
        }
    };

    int e = r0;
    for (; e + 1 < r1; e += 2) {
        float4 v0 = loadv(g_col[e]);
        float4 v1 = loadv(g_col[e + 1]);
        acc0.x += v0.x; acc0.y += v0.y; acc0.z += v0.z; acc0.w += v0.w;
        acc1.x += v1.x; acc1.y += v1.y; acc1.z += v1.z; acc1.w += v1.w;
    }
    if (e < r1) {
        float4 v0 = loadv(g_col[e]);
        acc0.x += v0.x; acc0.y += v0.y; acc0.z += v0.z; acc0.w += v0.w;
    }
    float inv = g_inv[node];
    float a = (acc0.x + acc1.x) * inv;
    float b = (acc0.y + acc1.y) * inv;
    float c = (acc0.z + acc1.z) * inv;
    float d = (acc0.w + acc1.w) * inv;
    __nv_bfloat162 h0, l0, h1, l1;
    split2(a, b, h0, l0);
    split2(c, d, h1, l1);
    size_t base = (size_t)node * D + lane * 4;
    *(__nv_bfloat162*)(g_gh + base)     = h0;
    *(__nv_bfloat162*)(g_gh + base + 2) = h1;
    *(__nv_bfloat162*)(g_gl + base)     = l0;
    *(__nv_bfloat162*)(g_gl + base + 2) = l1;
}

// ============== tensor-core fused dual GEMM (split-bf16, virtual K=768) ==============
__device__ __forceinline__ void mma16816(float c[4], uint32_t a0, uint32_t a1,
                                         uint32_t a2, uint32_t a3,
                                         uint32_t b0, uint32_t b1) {
    asm volatile(
        "mma.sync.aligned.m16n8k16.row.col.f32.bf16.bf16.f32 "
        "{%0,%1,%2,%3}, {%4,%5,%6,%7}, {%8,%9}, {%0,%1,%2,%3};\n"
        : "+f"(c[0]), "+f"(c[1]), "+f"(c[2]), "+f"(c[3])
        : "r"(a0), "r"(a1), "r"(a2), "r"(a3), "r"(b0), "r"(b1));
}

template <int LAYER>   // 1: relu, writes g_hh/g_hl ; 2: writes outp fp32
__global__ void __launch_bounds__(256, 2)
k_mma(const float* __restrict__ bias, float* __restrict__ outp, int Nn)
{
    __shared__ __nv_bfloat16 As[2][128 * PADK];
    __shared__ __nv_bfloat16 Bs[2][128 * PADK];

    const __nv_bfloat16* A2h = (LAYER == 1) ? g_xh : g_hh;
    const __nv_bfloat16* A2l = (LAYER == 1) ? g_xl : g_hl;
    const int wl = (LAYER == 1) ? 0 : 2;
    const int wr = (LAYER == 1) ? 1 : 3;
    const __nv_bfloat16* Wlh = g_wh + wl * D * D;
    const __nv_bfloat16* Wll = g_wl + wl * D * D;
    const __nv_bfloat16* Wrh = g_wh + wr * D * D;
    const __nv_bfloat16* Wrl = g_wl + wr * D * D;

    // virtual-K slabs (6 x 128): Ah@Wh, Al@Wh, Ah@Wl for each of two segments
    const __nv_bfloat16* Aslab[6] = {g_gh, g_gl, g_gh, A2h, A2l, A2h};
    const __nv_bfloat16* Wslab[6] = {Wlh,  Wlh,  Wll,  Wrh,  Wrh,  Wrl};

    int tid = threadIdx.x;
    int m0  = blockIdx.x * 128;
    int warp = tid >> 5, lane = tid & 31;
    int wm = (warp >> 2) * 64;      // 2 warps in m
    int wn = (warp & 3) * 32;       // 4 warps in n
    int g  = lane >> 2, ctg = lane & 3;

    float acc[4][4][4] = {};

    uint4 pa[2], pb[2];
    auto ldg_step = [&](int s) {
        int slab = s >> 2, koff = (s & 3) * 32;
        const __nv_bfloat16* Ap = Aslab[slab];
        const __nv_bfloat16* Wp = Wslab[slab];
#pragma unroll
        for (int l = 0; l < 2; l++) {
            int u = tid + l * 256;
            int row = u >> 2, kq = u & 3;
            int gm = m0 + row;
            uint4 va = make_uint4(0u, 0u, 0u, 0u);
            if (gm < Nn) va = *(const uint4*)(Ap + (size_t)gm * D + koff + kq * 8);
            pa[l] = va;
            pb[l] = *(const uint4*)(Wp + row * D + koff + kq * 8);
        }
    };
    auto sts_step = [&](int buf) {
#pragma unroll
        for (int l = 0; l < 2; l++) {
            int u = tid + l * 256;
            int row = u >> 2, kq = u & 3;
            *(uint4*)(&As[buf][row * PADK + kq * 8]) = pa[l];
            *(uint4*)(&Bs[buf][row * PADK + kq * 8]) = pb[l];
        }
    };
    auto compute = [&](int buf) {
#pragma unroll
        for (int p = 0; p < 2; p++) {
            uint32_t bfr[4][2];
#pragma unroll
            for (int ni = 0; ni < 4; ni++) {
                int n = wn + ni * 8 + g;
                const __nv_bfloat16* bp = &Bs[buf][n * PADK + p * 16 + ctg * 2];
                bfr[ni][0] = *(const uint32_t*)bp;
                bfr[ni][1] = *(const uint32_t*)(bp + 8);
            }
#pragma unroll
            for (int mi = 0; mi < 4; mi++) {
                int r = wm + mi * 16 + g;
                const __nv_bfloat16* ap = &As[buf][r * PADK + p * 16 + ctg * 2];
                uint32_t a0 = *(const uint32_t*)ap;
                uint32_t a1 = *(const uint32_t*)(ap + 8 * PADK);
                uint32_t a2 = *(const uint32_t*)(ap + 8);
                uint32_t a3 = *(const uint32_t*)(ap + 8 * PADK + 8);
#pragma unroll
                for (int ni = 0; ni < 4; ni++)
                    mma16816(acc[mi][ni], a0, a1, a2, a3, bfr[ni][0], bfr[ni][1]);
            }
        }
    };

    ldg_step(0);
    sts_step(0);
    __syncthreads();
    for (int s = 0; s < 24; s++) {
        if (s < 23) ldg_step(s + 1);
        compute(s & 1);
        if (s < 23) sts_step((s + 1) & 1);
        __syncthreads();
    }

    // epilogue
#pragma unroll
    for (int mi = 0; mi < 4; mi++) {
        int r0 = m0 + wm + mi * 16 + g;
        int r1 = r0 + 8;
#pragma unroll
        for (int ni = 0; ni < 4; ni++) {
            int col = wn + ni * 8 + ctg * 2;
            float2 b2 = *(const float2*)(bias + col);
            float v00 = acc[mi][ni][0] + b2.x, v01 = acc[mi][ni][1] + b2.y;
            float v10 = acc[mi][ni][2] + b2.x, v11 = acc[mi][ni][3] + b2.y;
            if (LAYER == 1) {
                v00 = fmaxf(v00, 0.f); v01 = fmaxf(v01, 0.f);
                v10 = fmaxf(v10, 0.f); v11 = fmaxf(v11, 0.f);
                if (r0 < Nn) {
                    size_t o = (size_t)r0 * D + col;
                    __nv_bfloat162 h2, l2; split2(v00, v01, h2, l2);
                    *(__nv_bfloat162*)(g_hh + o) = h2;
                    *(__nv_bfloat162*)(g_hl + o) = l2;
                }
                if (r1 < Nn) {
                    size_t o = (size_t)r1 * D + col;
                    __nv_bfloat162 h2, l2; split2(v10, v11, h2, l2);
                    *(__nv_bfloat162*)(g_hh + o) = h2;
                    *(__nv_bfloat162*)(g_hl + o) = l2;
                }
            } else {
                if (r0 < Nn) *(float2*)(outp + (size_t)r0 * D + col) = make_float2(v00, v01);
                if (r1 < Nn) *(float2*)(outp + (size_t)r1 * D + col) = make_float2(v10, v11);
            }
        }
    }
}

// ============================ launch ============================
extern "C" void kernel_launch(void* const* d_in, const int* in_sizes, int n_in,
                              void* d_out, int out_size)
{
    const float* x   = (const float*)d_in[0];
    const int*   ei  = (const int*)d_in[1];       // int32 (JAX x64 disabled)
    const float* w1l = (const float*)d_in[2];
    const float* b1  = (const float*)d_in[3];
    const float* w1r = (const float*)d_in[4];
    const float* w2l = (const float*)d_in[5];
    const float* b2  = (const float*)d_in[6];
    const float* w2r = (const float*)d_in[7];
    float*       out = (float*)d_out;

    int Nn = in_sizes[0] / D;
    int E  = in_sizes[1] / 2;
    const int* src = ei;
    const int* dst = ei + E;

    int FB = (E + 255) / 256;                  // fill blocks
    int XB = (Nn * (D / 4) + 255) / 256;       // x-split blocks
    int WB = (D * D + 255) / 256;              // W-split blocks

    // CSR build (scan-free) + operand splits: 3 launches
    k_deg<<<FB, 256>>>(dst, E, Nn);
    k_assign<<<(Nn + 255) / 256, 256>>>(Nn);
    k_fill_split<<<FB + XB + WB, 256>>>(src, dst, E, Nn, x, w1l, w1r, w2l, w2r, FB, XB);

    int aggBlocks  = (Nn * 32 + 255) / 256;
    int gemmBlocks = (Nn + 127) / 128;

    // layer 1: agg(x) -> g_gh/g_gl ; h = relu(agg@w1l^T + b1 + x@w1r^T) -> g_hh/g_hl
    k_agg<false><<<aggBlocks, 256>>>(x, Nn);
    k_mma<1><<<gemmBlocks, 256>>>(b1, nullptr, Nn);

    // layer 2: agg(h) -> g_gh/g_gl ; out = agg@w2l^T + b2 + h@w2r^T
    k_agg<true><<<aggBlocks, 256>>>(nullptr, Nn);
    k_mma<2><<<gemmBlocks, 256>>>(b2, out, Nn);
}